// round 2
// baseline (speedup 1.0000x reference)
#include <cuda_runtime.h>
#include <cstddef>

#define TT    243
#define NJ    17
#define BB    4
#define HH    8
#define HD    64
#define CC    512
#define EE    4
#define MROWS (BB*TT*NJ)   // 16524
#define NQKV  1536

// ---- scratch (static device globals; no allocations allowed) ----
__device__ float g_qkv[(size_t)MROWS * NQKV];   // ~101.5 MB
__device__ float g_gate[(size_t)MROWS * EE];
__device__ float g_eo[(size_t)MROWS * CC];      // ~33.8 MB

static __device__ __forceinline__ float warp_sum(float v) {
    #pragma unroll
    for (int o = 16; o; o >>= 1) v += __shfl_xor_sync(0xffffffffu, v, o);
    return v;
}
static __device__ __forceinline__ float warp_max(float v) {
    #pragma unroll
    for (int o = 16; o; o >>= 1) v = fmaxf(v, __shfl_xor_sync(0xffffffffu, v, o));
    return v;
}

// ============================================================================
// K1/K4: fp32 SGEMM, 128x128 block tile, BK=16, 256 threads, 8x8 microtile.
// C = A[MxK] * B[KxN] (+ bias). Requires K%16==0, N%128==0. M guarded.
// ============================================================================
template <bool BIAS>
__global__ __launch_bounds__(256) void sgemm128(
    const float* __restrict__ A, const float* __restrict__ B,
    const float* __restrict__ bias, float* __restrict__ C,
    int M, int N, int K)
{
    __shared__ float As[16][128];
    __shared__ float Bs[16][128];
    const int tid = threadIdx.x;
    const int tx = tid & 15, ty = tid >> 4;
    const int m0 = blockIdx.y * 128, n0 = blockIdx.x * 128;

    float acc[8][8];
    #pragma unroll
    for (int i = 0; i < 8; i++)
        #pragma unroll
        for (int j = 0; j < 8; j++) acc[i][j] = 0.f;

    for (int k0 = 0; k0 < K; k0 += 16) {
        #pragma unroll
        for (int l = 0; l < 2; l++) {
            int li = tid + l * 256;
            int ar = li >> 2, ac = (li & 3) * 4;
            int gr = m0 + ar;
            float4 av = (gr < M) ? *(const float4*)(A + (size_t)gr * K + k0 + ac)
                                 : make_float4(0.f, 0.f, 0.f, 0.f);
            As[ac + 0][ar] = av.x; As[ac + 1][ar] = av.y;
            As[ac + 2][ar] = av.z; As[ac + 3][ar] = av.w;
            int br = li >> 5, bc = (li & 31) * 4;
            float4 bv = *(const float4*)(B + (size_t)(k0 + br) * N + n0 + bc);
            *(float4*)&Bs[br][bc] = bv;
        }
        __syncthreads();
        #pragma unroll
        for (int kk = 0; kk < 16; kk++) {
            float4 a0 = *(const float4*)&As[kk][ty * 4];
            float4 a1 = *(const float4*)&As[kk][64 + ty * 4];
            float4 b0 = *(const float4*)&Bs[kk][tx * 4];
            float4 b1 = *(const float4*)&Bs[kk][64 + tx * 4];
            float ar8[8] = {a0.x, a0.y, a0.z, a0.w, a1.x, a1.y, a1.z, a1.w};
            float br8[8] = {b0.x, b0.y, b0.z, b0.w, b1.x, b1.y, b1.z, b1.w};
            #pragma unroll
            for (int i = 0; i < 8; i++)
                #pragma unroll
                for (int j = 0; j < 8; j++) acc[i][j] += ar8[i] * br8[j];
        }
        __syncthreads();
    }

    #pragma unroll
    for (int ih = 0; ih < 2; ih++)
        #pragma unroll
        for (int i = 0; i < 4; i++) {
            int r = m0 + ih * 64 + ty * 4 + i;
            if (r >= M) continue;
            #pragma unroll
            for (int jh = 0; jh < 2; jh++) {
                int cb = n0 + jh * 64 + tx * 4;
                float4 o;
                o.x = acc[ih * 4 + i][jh * 4 + 0];
                o.y = acc[ih * 4 + i][jh * 4 + 1];
                o.z = acc[ih * 4 + i][jh * 4 + 2];
                o.w = acc[ih * 4 + i][jh * 4 + 3];
                if (BIAS) {
                    o.x += bias[cb + 0]; o.y += bias[cb + 1];
                    o.z += bias[cb + 2]; o.w += bias[cb + 3];
                }
                *(float4*)(C + (size_t)r * N + cb) = o;
            }
        }
}

// ============================================================================
// K2: gating — one warp per token row: softmax(x @ te_w + te_b) over E=4
// ============================================================================
__global__ __launch_bounds__(256) void gate_kernel(
    const float* __restrict__ x, const float* __restrict__ tw,
    const float* __restrict__ tb, float* __restrict__ gate)
{
    int row = blockIdx.x * 8 + (threadIdx.x >> 5);
    if (row >= MROWS) return;
    int lane = threadIdx.x & 31;
    const float* xr = x + (size_t)row * CC;
    float s0 = 0.f, s1 = 0.f, s2 = 0.f, s3 = 0.f;
    for (int c = lane; c < CC; c += 32) {
        float xv = xr[c];
        float4 w = *(const float4*)(tw + c * 4);
        s0 += xv * w.x; s1 += xv * w.y; s2 += xv * w.z; s3 += xv * w.w;
    }
    s0 = warp_sum(s0); s1 = warp_sum(s1); s2 = warp_sum(s2); s3 = warp_sum(s3);
    float l0 = s0 + tb[0], l1 = s1 + tb[1], l2 = s2 + tb[2], l3 = s3 + tb[3];
    float m = fmaxf(fmaxf(l0, l1), fmaxf(l2, l3));
    float e0 = __expf(l0 - m), e1 = __expf(l1 - m);
    float e2 = __expf(l2 - m), e3 = __expf(l3 - m);
    float inv = 1.f / (e0 + e1 + e2 + e3);
    if (lane == 0) {
        float4 o = make_float4(e0 * inv, e1 * inv, e2 * inv, e3 * inv);
        *(float4*)(gate + (size_t)row * 4) = o;
    }
}

// ============================================================================
// K3: attention — one CTA per (b,h,n). K/V resident in SMEM.
// Per 64-row Q tile: S = Q K^T -> nested-window softmax folded with gate
// coefficients into a single combined attention matrix -> O = P V.
// ============================================================================
#define SK_ROWS  256
#define SK_PITCH 65
#define SV_ROWS  244
#define SQ_PITCH 65
#define SP_PITCH 248
#define ATTN_SMEM_FLOATS (SK_ROWS*SK_PITCH + SV_ROWS*HD + 64*SQ_PITCH + 64*SP_PITCH)
#define ATTN_SMEM_BYTES  (ATTN_SMEM_FLOATS * 4)

__global__ __launch_bounds__(256) void attn_kernel(
    const float* __restrict__ qkv, const float* __restrict__ gate,
    float* __restrict__ eo)
{
    extern __shared__ float sm[];
    float* sK = sm;                               // [256][65]
    float* sV = sK + SK_ROWS * SK_PITCH;          // [244][64]
    float* sQ = sV + SV_ROWS * HD;                // [64][65]
    float* sP = sQ + 64 * SQ_PITCH;               // [64][248]

    const int tid = threadIdx.x;
    const int tx = tid & 15, ty = tid >> 4;
    const int lane = tid & 31, warp = tid >> 5;
    const int bid = blockIdx.x;
    const int b = bid / (HH * NJ);
    const int h = (bid / NJ) % HH;
    const int n = bid % NJ;
    const float scale = 0.125f;  // HEAD^-0.5

    // ---- load K, V for this (b,h,n) ----
    for (int i = tid; i < TT * 16; i += 256) {
        int s = i >> 4, c4 = (i & 15) * 4;
        const float* src = qkv + ((size_t)((b * TT + s) * NJ + n)) * NQKV + h * HD;
        float4 kv = *(const float4*)(src + 512 + c4);
        sK[s * SK_PITCH + c4 + 0] = kv.x;
        sK[s * SK_PITCH + c4 + 1] = kv.y;
        sK[s * SK_PITCH + c4 + 2] = kv.z;
        sK[s * SK_PITCH + c4 + 3] = kv.w;
        float4 vv = *(const float4*)(src + 1024 + c4);
        *(float4*)&sV[s * HD + c4] = vv;
    }
    // zero-pad K rows [243,256) and V row 243
    for (int i = tid; i < (SK_ROWS - TT) * HD; i += 256) {
        int s = TT + i / HD, c = i % HD;
        sK[s * SK_PITCH + c] = 0.f;
    }
    for (int i = tid; i < (SV_ROWS - TT) * HD; i += 256)
        sV[TT * HD + i] = 0.f;

    for (int t0 = 0; t0 < TT; t0 += 64) {
        // ---- load Q tile ----
        for (int i = tid; i < 64 * 16; i += 256) {
            int r = i >> 4, c4 = (i & 15) * 4;
            int t = t0 + r;
            float4 qv = (t < TT)
                ? *(const float4*)(qkv + ((size_t)((b * TT + t) * NJ + n)) * NQKV + h * HD + c4)
                : make_float4(0.f, 0.f, 0.f, 0.f);
            sQ[r * SQ_PITCH + c4 + 0] = qv.x;
            sQ[r * SQ_PITCH + c4 + 1] = qv.y;
            sQ[r * SQ_PITCH + c4 + 2] = qv.z;
            sQ[r * SQ_PITCH + c4 + 3] = qv.w;
        }
        __syncthreads();

        // ---- GEMM1: S[r][s], r = 4*ty+i (4 rows), s = tx+16*j (16 cols) ----
        {
            float acc[4][16];
            #pragma unroll
            for (int i = 0; i < 4; i++)
                #pragma unroll
                for (int j = 0; j < 16; j++) acc[i][j] = 0.f;
            #pragma unroll 4
            for (int kk = 0; kk < HD; kk++) {
                float qf[4];
                #pragma unroll
                for (int i = 0; i < 4; i++) qf[i] = sQ[(4 * ty + i) * SQ_PITCH + kk];
                #pragma unroll
                for (int j = 0; j < 16; j++) {
                    float kf = sK[(tx + 16 * j) * SK_PITCH + kk];
                    #pragma unroll
                    for (int i = 0; i < 4; i++) acc[i][j] += qf[i] * kf;
                }
            }
            #pragma unroll
            for (int i = 0; i < 4; i++)
                #pragma unroll
                for (int j = 0; j < 16; j++) {
                    int s = tx + 16 * j;
                    if (s < 244) sP[(4 * ty + i) * SP_PITCH + s] = acc[i][j] * scale;
                }
        }
        __syncthreads();

        // ---- nested-window softmax + gate folding (warp per row, 8 rows/warp) ----
        for (int rr = 0; rr < 8; rr++) {
            int r = warp * 8 + rr;
            int t = t0 + r;
            if (t >= TT) break;
            float p[8];
            float m = -1e30f;
            #pragma unroll
            for (int i2 = 0; i2 < 8; i2++) {
                int s = lane + 32 * i2;
                float v = (s < TT) ? sP[r * SP_PITCH + s] : -1e30f;
                p[i2] = v;
                m = fmaxf(m, v);
            }
            m = warp_max(m);
            int a9 = (t / 9) * 9, a27 = (t / 27) * 27, a81 = (t / 81) * 81;
            float z9 = 0.f, z27 = 0.f, z81 = 0.f, z243 = 0.f;
            #pragma unroll
            for (int i2 = 0; i2 < 8; i2++) {
                int s = lane + 32 * i2;
                float e = (s < TT) ? __expf(p[i2] - m) : 0.f;
                p[i2] = e;
                z243 += e;
                if (s >= a81 && s < a81 + 81) z81 += e;
                if (s >= a27 && s < a27 + 27) z27 += e;
                if (s >= a9  && s < a9  + 9)  z9  += e;
            }
            z9 = warp_sum(z9); z27 = warp_sum(z27);
            z81 = warp_sum(z81); z243 = warp_sum(z243);
            const float* gr = gate + ((size_t)((b * TT + t) * NJ + n)) * 4;
            float w9 = gr[0] / z9, w27 = gr[1] / z27;
            float w81 = gr[2] / z81, w243 = gr[3] / z243;
            #pragma unroll
            for (int i2 = 0; i2 < 8; i2++) {
                int s = lane + 32 * i2;
                if (s < SP_PITCH) {
                    float cf = w243;
                    if (s >= a81 && s < a81 + 81) cf += w81;
                    if (s >= a27 && s < a27 + 27) cf += w27;
                    if (s >= a9  && s < a9  + 9)  cf += w9;
                    sP[r * SP_PITCH + s] = (s < TT) ? p[i2] * cf : 0.f;
                }
            }
        }
        __syncthreads();

        // ---- GEMM2: O = P[64x244] @ V[244x64]; micro 4x4, float4 over kk ----
        {
            float acc2[4][4];
            #pragma unroll
            for (int i = 0; i < 4; i++)
                #pragma unroll
                for (int j = 0; j < 4; j++) acc2[i][j] = 0.f;
            for (int kk = 0; kk < 244; kk += 4) {
                float4 pv[4];
                #pragma unroll
                for (int i = 0; i < 4; i++)
                    pv[i] = *(const float4*)&sP[(4 * ty + i) * SP_PITCH + kk];
                #pragma unroll
                for (int u = 0; u < 4; u++) {
                    float4 vv = *(const float4*)&sV[(kk + u) * HD + tx * 4];
                    float pu[4];
                    pu[0] = ((const float*)&pv[0])[u];
                    pu[1] = ((const float*)&pv[1])[u];
                    pu[2] = ((const float*)&pv[2])[u];
                    pu[3] = ((const float*)&pv[3])[u];
                    #pragma unroll
                    for (int i = 0; i < 4; i++) {
                        acc2[i][0] += pu[i] * vv.x;
                        acc2[i][1] += pu[i] * vv.y;
                        acc2[i][2] += pu[i] * vv.z;
                        acc2[i][3] += pu[i] * vv.w;
                    }
                }
            }
            #pragma unroll
            for (int i = 0; i < 4; i++) {
                int t = t0 + 4 * ty + i;
                if (t < TT) {
                    float4 o = make_float4(acc2[i][0], acc2[i][1], acc2[i][2], acc2[i][3]);
                    *(float4*)(eo + ((size_t)((b * TT + t) * NJ + n)) * CC + h * HD + tx * 4) = o;
                }
            }
        }
        __syncthreads();
    }
}

// ============================================================================
extern "C" void kernel_launch(void* const* d_in, const int* in_sizes, int n_in,
                              void* d_out, int out_size)
{
    const float* x      = (const float*)d_in[0];
    const float* qkv_w  = (const float*)d_in[1];
    const float* proj_w = (const float*)d_in[2];
    const float* proj_b = (const float*)d_in[3];
    const float* te_w   = (const float*)d_in[4];
    const float* te_b   = (const float*)d_in[5];
    float* out = (float*)d_out;

    float *qkv_p, *gate_p, *eo_p;
    cudaGetSymbolAddress((void**)&qkv_p,  g_qkv);
    cudaGetSymbolAddress((void**)&gate_p, g_gate);
    cudaGetSymbolAddress((void**)&eo_p,   g_eo);

    cudaFuncSetAttribute(attn_kernel, cudaFuncAttributeMaxDynamicSharedMemorySize,
                         ATTN_SMEM_BYTES);

    // K1: qkv = x @ qkv_w   (16524 x 1536 x 512)
    sgemm128<false><<<dim3(NQKV / 128, (MROWS + 127) / 128), 256>>>(
        x, qkv_w, nullptr, qkv_p, MROWS, NQKV, CC);

    // K2: gate = softmax(x @ te_w + te_b)
    gate_kernel<<<(MROWS + 7) / 8, 256>>>(x, te_w, te_b, gate_p);

    // K3: fused multi-window attention + expert recombination
    attn_kernel<<<BB * HH * NJ, 256, ATTN_SMEM_BYTES>>>(qkv_p, gate_p, eo_p);

    // K4: out = eo @ proj_w + proj_b   (16524 x 512 x 512)
    sgemm128<true><<<dim3(CC / 128, (MROWS + 127) / 128), 256>>>(
        eo_p, proj_w, proj_b, out, MROWS, CC, CC);
}

// round 3
// speedup vs baseline: 1.6189x; 1.6189x over previous
#include <cuda_runtime.h>
#include <cstdint>
#include <cstddef>

#define TT    243
#define NJ    17
#define BB    4
#define HH    8
#define HD    64
#define CC    512
#define EE    4
#define MROWS (BB*TT*NJ)   // 16524
#define NQKV  1536

// ---- scratch (static device globals; no allocations allowed) ----
__device__ float g_qkv[(size_t)MROWS * NQKV];   // ~101.5 MB
__device__ float g_gate[(size_t)MROWS * EE];
__device__ float g_eo[(size_t)MROWS * CC];      // ~33.8 MB

static __device__ __forceinline__ float warp_sum(float v) {
    #pragma unroll
    for (int o = 16; o; o >>= 1) v += __shfl_xor_sync(0xffffffffu, v, o);
    return v;
}
static __device__ __forceinline__ float warp_max(float v) {
    #pragma unroll
    for (int o = 16; o; o >>= 1) v = fmaxf(v, __shfl_xor_sync(0xffffffffu, v, o));
    return v;
}

static __device__ __forceinline__ uint32_t f2tf32(float x) {
    uint32_t r;
    asm("cvt.rna.tf32.f32 %0, %1;" : "=r"(r) : "f"(x));
    return r;
}

// ============================================================================
// K1/K4: tf32 tensor-core GEMM. C = A[MxK]*B[KxN] (+bias).
// BM=BN=128, BK=16, 256 threads, 8 warps (2m x 4n), warptile 64x32.
// mma.sync.aligned.m16n8k8.row.col.f32.tf32.tf32.f32, fp32 accum.
// Requires K%16==0, N%128==0; M guarded.
// ============================================================================
#define AP 20    // As pitch (floats):  bank-conflict-free fragment loads
#define BP 136   // Bs pitch (floats):  bank-conflict-free fragment loads

template <bool BIAS>
__global__ __launch_bounds__(256) void gemm_tf32(
    const float* __restrict__ A, const float* __restrict__ B,
    const float* __restrict__ bias, float* __restrict__ C,
    int M, int N, int K)
{
    __shared__ float As[128 * AP];
    __shared__ float Bs[16 * BP];

    const int tid  = threadIdx.x;
    const int warp = tid >> 5, lane = tid & 31;
    const int g    = lane >> 2, tig = lane & 3;
    const int wm   = warp & 1,  wn  = warp >> 1;      // 2 x 4 warp grid
    const int m0   = blockIdx.y * 128, n0 = blockIdx.x * 128;

    float c[4][4][4];   // [mt][nt][frag]
    #pragma unroll
    for (int i = 0; i < 4; i++)
        #pragma unroll
        for (int j = 0; j < 4; j++)
            #pragma unroll
            for (int f = 0; f < 4; f++) c[i][j][f] = 0.f;

    for (int k0 = 0; k0 < K; k0 += 16) {
        // ---- stage A (128x16) and B (16x128), converting to tf32 ----
        #pragma unroll
        for (int l = 0; l < 2; l++) {
            int li = tid + l * 256;
            // A: 128 rows x 4 float4
            int ar = li >> 2, ac4 = (li & 3) * 4;
            int gr = m0 + ar;
            float4 av = (gr < M) ? *(const float4*)(A + (size_t)gr * K + k0 + ac4)
                                 : make_float4(0.f, 0.f, 0.f, 0.f);
            uint4 at;
            at.x = f2tf32(av.x); at.y = f2tf32(av.y);
            at.z = f2tf32(av.z); at.w = f2tf32(av.w);
            *(uint4*)&As[ar * AP + ac4] = at;
            // B: 16 rows x 32 float4
            int br = li >> 5, bc4 = (li & 31) * 4;
            float4 bv = *(const float4*)(B + (size_t)(k0 + br) * N + n0 + bc4);
            uint4 bt;
            bt.x = f2tf32(bv.x); bt.y = f2tf32(bv.y);
            bt.z = f2tf32(bv.z); bt.w = f2tf32(bv.w);
            *(uint4*)&Bs[br * BP + bc4] = bt;
        }
        __syncthreads();

        #pragma unroll
        for (int kk = 0; kk < 16; kk += 8) {
            // ---- fragment loads ----
            uint32_t af[4][4];
            #pragma unroll
            for (int mt = 0; mt < 4; mt++) {
                int base = wm * 64 + mt * 16;
                af[mt][0] = __float_as_uint(As[(base + g)     * AP + kk + tig]);
                af[mt][1] = __float_as_uint(As[(base + g + 8) * AP + kk + tig]);
                af[mt][2] = __float_as_uint(As[(base + g)     * AP + kk + tig + 4]);
                af[mt][3] = __float_as_uint(As[(base + g + 8) * AP + kk + tig + 4]);
            }
            uint32_t bf[4][2];
            #pragma unroll
            for (int nt = 0; nt < 4; nt++) {
                int n = wn * 32 + nt * 8 + g;
                bf[nt][0] = __float_as_uint(Bs[(kk + tig)     * BP + n]);
                bf[nt][1] = __float_as_uint(Bs[(kk + tig + 4) * BP + n]);
            }
            // ---- 16 mmas ----
            #pragma unroll
            for (int mt = 0; mt < 4; mt++)
                #pragma unroll
                for (int nt = 0; nt < 4; nt++) {
                    asm volatile(
                        "mma.sync.aligned.m16n8k8.row.col.f32.tf32.tf32.f32 "
                        "{%0,%1,%2,%3}, {%4,%5,%6,%7}, {%8,%9}, {%0,%1,%2,%3};\n"
                        : "+f"(c[mt][nt][0]), "+f"(c[mt][nt][1]),
                          "+f"(c[mt][nt][2]), "+f"(c[mt][nt][3])
                        : "r"(af[mt][0]), "r"(af[mt][1]),
                          "r"(af[mt][2]), "r"(af[mt][3]),
                          "r"(bf[nt][0]), "r"(bf[nt][1]));
                }
        }
        __syncthreads();
    }

    // ---- epilogue ----
    #pragma unroll
    for (int mt = 0; mt < 4; mt++) {
        int row0 = m0 + wm * 64 + mt * 16 + g;
        #pragma unroll
        for (int nt = 0; nt < 4; nt++) {
            int col = n0 + wn * 32 + nt * 8 + 2 * tig;
            float b0 = 0.f, b1 = 0.f;
            if (BIAS) { b0 = bias[col]; b1 = bias[col + 1]; }
            if (row0 < M) {
                float2 o = make_float2(c[mt][nt][0] + b0, c[mt][nt][1] + b1);
                *(float2*)(C + (size_t)row0 * N + col) = o;
            }
            if (row0 + 8 < M) {
                float2 o = make_float2(c[mt][nt][2] + b0, c[mt][nt][3] + b1);
                *(float2*)(C + (size_t)(row0 + 8) * N + col) = o;
            }
        }
    }
}

// ============================================================================
// K2: gating — one warp per token row: softmax(x @ te_w + te_b) over E=4
// ============================================================================
__global__ __launch_bounds__(256) void gate_kernel(
    const float* __restrict__ x, const float* __restrict__ tw,
    const float* __restrict__ tb, float* __restrict__ gate)
{
    int row = blockIdx.x * 8 + (threadIdx.x >> 5);
    if (row >= MROWS) return;
    int lane = threadIdx.x & 31;
    const float* xr = x + (size_t)row * CC;
    float s0 = 0.f, s1 = 0.f, s2 = 0.f, s3 = 0.f;
    for (int c = lane; c < CC; c += 32) {
        float xv = xr[c];
        float4 w = *(const float4*)(tw + c * 4);
        s0 += xv * w.x; s1 += xv * w.y; s2 += xv * w.z; s3 += xv * w.w;
    }
    s0 = warp_sum(s0); s1 = warp_sum(s1); s2 = warp_sum(s2); s3 = warp_sum(s3);
    float l0 = s0 + tb[0], l1 = s1 + tb[1], l2 = s2 + tb[2], l3 = s3 + tb[3];
    float m = fmaxf(fmaxf(l0, l1), fmaxf(l2, l3));
    float e0 = __expf(l0 - m), e1 = __expf(l1 - m);
    float e2 = __expf(l2 - m), e3 = __expf(l3 - m);
    float inv = 1.f / (e0 + e1 + e2 + e3);
    if (lane == 0) {
        float4 o = make_float4(e0 * inv, e1 * inv, e2 * inv, e3 * inv);
        *(float4*)(gate + (size_t)row * 4) = o;
    }
}

// ============================================================================
// K3: attention — one CTA per (b,h,n). K/V resident in SMEM.
// Per 64-row Q tile: S = Q K^T -> nested-window softmax folded with gate
// coefficients into a single combined attention matrix -> O = P V.
// ============================================================================
#define SK_ROWS  256
#define SK_PITCH 65
#define SV_ROWS  244
#define SQ_PITCH 65
#define SP_PITCH 248
#define ATTN_SMEM_FLOATS (SK_ROWS*SK_PITCH + SV_ROWS*HD + 64*SQ_PITCH + 64*SP_PITCH)
#define ATTN_SMEM_BYTES  (ATTN_SMEM_FLOATS * 4)

__global__ __launch_bounds__(256) void attn_kernel(
    const float* __restrict__ qkv, const float* __restrict__ gate,
    float* __restrict__ eo)
{
    extern __shared__ float sm[];
    float* sK = sm;                               // [256][65]
    float* sV = sK + SK_ROWS * SK_PITCH;          // [244][64]
    float* sQ = sV + SV_ROWS * HD;                // [64][65]
    float* sP = sQ + 64 * SQ_PITCH;               // [64][248]

    const int tid = threadIdx.x;
    const int tx = tid & 15, ty = tid >> 4;
    const int lane = tid & 31, warp = tid >> 5;
    const int bid = blockIdx.x;
    const int b = bid / (HH * NJ);
    const int h = (bid / NJ) % HH;
    const int n = bid % NJ;
    const float scale = 0.125f;  // HEAD^-0.5

    // ---- load K, V for this (b,h,n) ----
    for (int i = tid; i < TT * 16; i += 256) {
        int s = i >> 4, c4 = (i & 15) * 4;
        const float* src = qkv + ((size_t)((b * TT + s) * NJ + n)) * NQKV + h * HD;
        float4 kv = *(const float4*)(src + 512 + c4);
        sK[s * SK_PITCH + c4 + 0] = kv.x;
        sK[s * SK_PITCH + c4 + 1] = kv.y;
        sK[s * SK_PITCH + c4 + 2] = kv.z;
        sK[s * SK_PITCH + c4 + 3] = kv.w;
        float4 vv = *(const float4*)(src + 1024 + c4);
        *(float4*)&sV[s * HD + c4] = vv;
    }
    // zero-pad K rows [243,256) and V row 243
    for (int i = tid; i < (SK_ROWS - TT) * HD; i += 256) {
        int s = TT + i / HD, c = i % HD;
        sK[s * SK_PITCH + c] = 0.f;
    }
    for (int i = tid; i < (SV_ROWS - TT) * HD; i += 256)
        sV[TT * HD + i] = 0.f;

    for (int t0 = 0; t0 < TT; t0 += 64) {
        // ---- load Q tile ----
        for (int i = tid; i < 64 * 16; i += 256) {
            int r = i >> 4, c4 = (i & 15) * 4;
            int t = t0 + r;
            float4 qv = (t < TT)
                ? *(const float4*)(qkv + ((size_t)((b * TT + t) * NJ + n)) * NQKV + h * HD + c4)
                : make_float4(0.f, 0.f, 0.f, 0.f);
            sQ[r * SQ_PITCH + c4 + 0] = qv.x;
            sQ[r * SQ_PITCH + c4 + 1] = qv.y;
            sQ[r * SQ_PITCH + c4 + 2] = qv.z;
            sQ[r * SQ_PITCH + c4 + 3] = qv.w;
        }
        __syncthreads();

        // ---- GEMM1: S[r][s], r = 4*ty+i (4 rows), s = tx+16*j (16 cols) ----
        {
            float acc[4][16];
            #pragma unroll
            for (int i = 0; i < 4; i++)
                #pragma unroll
                for (int j = 0; j < 16; j++) acc[i][j] = 0.f;
            #pragma unroll 4
            for (int kk = 0; kk < HD; kk++) {
                float qf[4];
                #pragma unroll
                for (int i = 0; i < 4; i++) qf[i] = sQ[(4 * ty + i) * SQ_PITCH + kk];
                #pragma unroll
                for (int j = 0; j < 16; j++) {
                    float kf = sK[(tx + 16 * j) * SK_PITCH + kk];
                    #pragma unroll
                    for (int i = 0; i < 4; i++) acc[i][j] += qf[i] * kf;
                }
            }
            #pragma unroll
            for (int i = 0; i < 4; i++)
                #pragma unroll
                for (int j = 0; j < 16; j++) {
                    int s = tx + 16 * j;
                    if (s < 244) sP[(4 * ty + i) * SP_PITCH + s] = acc[i][j] * scale;
                }
        }
        __syncthreads();

        // ---- nested-window softmax + gate folding (warp per row, 8 rows/warp) ----
        for (int rr = 0; rr < 8; rr++) {
            int r = warp * 8 + rr;
            int t = t0 + r;
            if (t >= TT) break;
            float p[8];
            float m = -1e30f;
            #pragma unroll
            for (int i2 = 0; i2 < 8; i2++) {
                int s = lane + 32 * i2;
                float v = (s < TT) ? sP[r * SP_PITCH + s] : -1e30f;
                p[i2] = v;
                m = fmaxf(m, v);
            }
            m = warp_max(m);
            int a9 = (t / 9) * 9, a27 = (t / 27) * 27, a81 = (t / 81) * 81;
            float z9 = 0.f, z27 = 0.f, z81 = 0.f, z243 = 0.f;
            #pragma unroll
            for (int i2 = 0; i2 < 8; i2++) {
                int s = lane + 32 * i2;
                float e = (s < TT) ? __expf(p[i2] - m) : 0.f;
                p[i2] = e;
                z243 += e;
                if (s >= a81 && s < a81 + 81) z81 += e;
                if (s >= a27 && s < a27 + 27) z27 += e;
                if (s >= a9  && s < a9  + 9)  z9  += e;
            }
            z9 = warp_sum(z9); z27 = warp_sum(z27);
            z81 = warp_sum(z81); z243 = warp_sum(z243);
            const float* gr = gate + ((size_t)((b * TT + t) * NJ + n)) * 4;
            float w9 = gr[0] / z9, w27 = gr[1] / z27;
            float w81 = gr[2] / z81, w243 = gr[3] / z243;
            #pragma unroll
            for (int i2 = 0; i2 < 8; i2++) {
                int s = lane + 32 * i2;
                if (s < SP_PITCH) {
                    float cf = w243;
                    if (s >= a81 && s < a81 + 81) cf += w81;
                    if (s >= a27 && s < a27 + 27) cf += w27;
                    if (s >= a9  && s < a9  + 9)  cf += w9;
                    sP[r * SP_PITCH + s] = (s < TT) ? p[i2] * cf : 0.f;
                }
            }
        }
        __syncthreads();

        // ---- GEMM2: O = P[64x244] @ V[244x64]; micro 4x4, float4 over kk ----
        {
            float acc2[4][4];
            #pragma unroll
            for (int i = 0; i < 4; i++)
                #pragma unroll
                for (int j = 0; j < 4; j++) acc2[i][j] = 0.f;
            for (int kk = 0; kk < 244; kk += 4) {
                float4 pv[4];
                #pragma unroll
                for (int i = 0; i < 4; i++)
                    pv[i] = *(const float4*)&sP[(4 * ty + i) * SP_PITCH + kk];
                #pragma unroll
                for (int u = 0; u < 4; u++) {
                    float4 vv = *(const float4*)&sV[(kk + u) * HD + tx * 4];
                    float pu[4];
                    pu[0] = ((const float*)&pv[0])[u];
                    pu[1] = ((const float*)&pv[1])[u];
                    pu[2] = ((const float*)&pv[2])[u];
                    pu[3] = ((const float*)&pv[3])[u];
                    #pragma unroll
                    for (int i = 0; i < 4; i++) {
                        acc2[i][0] += pu[i] * vv.x;
                        acc2[i][1] += pu[i] * vv.y;
                        acc2[i][2] += pu[i] * vv.z;
                        acc2[i][3] += pu[i] * vv.w;
                    }
                }
            }
            #pragma unroll
            for (int i = 0; i < 4; i++) {
                int t = t0 + 4 * ty + i;
                if (t < TT) {
                    float4 o = make_float4(acc2[i][0], acc2[i][1], acc2[i][2], acc2[i][3]);
                    *(float4*)(eo + ((size_t)((b * TT + t) * NJ + n)) * CC + h * HD + tx * 4) = o;
                }
            }
        }
        __syncthreads();
    }
}

// ============================================================================
extern "C" void kernel_launch(void* const* d_in, const int* in_sizes, int n_in,
                              void* d_out, int out_size)
{
    const float* x      = (const float*)d_in[0];
    const float* qkv_w  = (const float*)d_in[1];
    const float* proj_w = (const float*)d_in[2];
    const float* proj_b = (const float*)d_in[3];
    const float* te_w   = (const float*)d_in[4];
    const float* te_b   = (const float*)d_in[5];
    float* out = (float*)d_out;

    float *qkv_p, *gate_p, *eo_p;
    cudaGetSymbolAddress((void**)&qkv_p,  g_qkv);
    cudaGetSymbolAddress((void**)&gate_p, g_gate);
    cudaGetSymbolAddress((void**)&eo_p,   g_eo);

    cudaFuncSetAttribute(attn_kernel, cudaFuncAttributeMaxDynamicSharedMemorySize,
                         ATTN_SMEM_BYTES);

    // K1: qkv = x @ qkv_w   (16524 x 1536 x 512)  — tf32 tensor cores
    gemm_tf32<false><<<dim3(NQKV / 128, (MROWS + 127) / 128), 256>>>(
        x, qkv_w, nullptr, qkv_p, MROWS, NQKV, CC);

    // K2: gate = softmax(x @ te_w + te_b)
    gate_kernel<<<(MROWS + 7) / 8, 256>>>(x, te_w, te_b, gate_p);

    // K3: fused multi-window attention + expert recombination
    attn_kernel<<<BB * HH * NJ, 256, ATTN_SMEM_BYTES>>>(qkv_p, gate_p, eo_p);

    // K4: out = eo @ proj_w + proj_b   (16524 x 512 x 512) — tf32 tensor cores
    gemm_tf32<true><<<dim3(CC / 128, (MROWS + 127) / 128), 256>>>(
        eo_p, proj_w, proj_b, out, MROWS, CC, CC);
}

// round 4
// speedup vs baseline: 1.7658x; 1.0907x over previous
#include <cuda_runtime.h>
#include <cstdint>
#include <cstddef>

#define TT    243
#define NJ    17
#define BB    4
#define HH    8
#define HD    64
#define CC    512
#define EE    4
#define MROWS (BB*TT*NJ)   // 16524
#define NQKV  1536

// ---- scratch (static device globals; no allocations allowed) ----
__device__ float g_qkv[(size_t)MROWS * NQKV];   // ~101.5 MB
__device__ float g_gate[(size_t)MROWS * EE];
__device__ float g_eo[(size_t)MROWS * CC];      // ~33.8 MB

static __device__ __forceinline__ float warp_sum(float v) {
    #pragma unroll
    for (int o = 16; o; o >>= 1) v += __shfl_xor_sync(0xffffffffu, v, o);
    return v;
}
static __device__ __forceinline__ float warp_max(float v) {
    #pragma unroll
    for (int o = 16; o; o >>= 1) v = fmaxf(v, __shfl_xor_sync(0xffffffffu, v, o));
    return v;
}

static __device__ __forceinline__ uint32_t f2tf32(float x) {
    uint32_t r;
    asm("cvt.rna.tf32.f32 %0, %1;" : "=r"(r) : "f"(x));
    return r;
}

static __device__ __forceinline__ void mma_m16n8k8(
    float* c, const uint32_t* a, const uint32_t* b)
{
    asm volatile(
        "mma.sync.aligned.m16n8k8.row.col.f32.tf32.tf32.f32 "
        "{%0,%1,%2,%3}, {%4,%5,%6,%7}, {%8,%9}, {%0,%1,%2,%3};\n"
        : "+f"(c[0]), "+f"(c[1]), "+f"(c[2]), "+f"(c[3])
        : "r"(a[0]), "r"(a[1]), "r"(a[2]), "r"(a[3]),
          "r"(b[0]), "r"(b[1]));
}

// ============================================================================
// K1/K4: tf32 tensor-core GEMM. (unchanged from R2)
// ============================================================================
#define AP 20
#define BP 136

template <bool BIAS>
__global__ __launch_bounds__(256) void gemm_tf32(
    const float* __restrict__ A, const float* __restrict__ B,
    const float* __restrict__ bias, float* __restrict__ C,
    int M, int N, int K)
{
    __shared__ float As[128 * AP];
    __shared__ float Bs[16 * BP];

    const int tid  = threadIdx.x;
    const int warp = tid >> 5, lane = tid & 31;
    const int g    = lane >> 2, tig = lane & 3;
    const int wm   = warp & 1,  wn  = warp >> 1;
    const int m0   = blockIdx.y * 128, n0 = blockIdx.x * 128;

    float c[4][4][4];
    #pragma unroll
    for (int i = 0; i < 4; i++)
        #pragma unroll
        for (int j = 0; j < 4; j++)
            #pragma unroll
            for (int f = 0; f < 4; f++) c[i][j][f] = 0.f;

    for (int k0 = 0; k0 < K; k0 += 16) {
        #pragma unroll
        for (int l = 0; l < 2; l++) {
            int li = tid + l * 256;
            int ar = li >> 2, ac4 = (li & 3) * 4;
            int gr = m0 + ar;
            float4 av = (gr < M) ? *(const float4*)(A + (size_t)gr * K + k0 + ac4)
                                 : make_float4(0.f, 0.f, 0.f, 0.f);
            uint4 at;
            at.x = f2tf32(av.x); at.y = f2tf32(av.y);
            at.z = f2tf32(av.z); at.w = f2tf32(av.w);
            *(uint4*)&As[ar * AP + ac4] = at;
            int br = li >> 5, bc4 = (li & 31) * 4;
            float4 bv = *(const float4*)(B + (size_t)(k0 + br) * N + n0 + bc4);
            uint4 bt;
            bt.x = f2tf32(bv.x); bt.y = f2tf32(bv.y);
            bt.z = f2tf32(bv.z); bt.w = f2tf32(bv.w);
            *(uint4*)&Bs[br * BP + bc4] = bt;
        }
        __syncthreads();

        #pragma unroll
        for (int kk = 0; kk < 16; kk += 8) {
            uint32_t af[4][4];
            #pragma unroll
            for (int mt = 0; mt < 4; mt++) {
                int base = wm * 64 + mt * 16;
                af[mt][0] = __float_as_uint(As[(base + g)     * AP + kk + tig]);
                af[mt][1] = __float_as_uint(As[(base + g + 8) * AP + kk + tig]);
                af[mt][2] = __float_as_uint(As[(base + g)     * AP + kk + tig + 4]);
                af[mt][3] = __float_as_uint(As[(base + g + 8) * AP + kk + tig + 4]);
            }
            uint32_t bf[4][2];
            #pragma unroll
            for (int nt = 0; nt < 4; nt++) {
                int n = wn * 32 + nt * 8 + g;
                bf[nt][0] = __float_as_uint(Bs[(kk + tig)     * BP + n]);
                bf[nt][1] = __float_as_uint(Bs[(kk + tig + 4) * BP + n]);
            }
            #pragma unroll
            for (int mt = 0; mt < 4; mt++)
                #pragma unroll
                for (int nt = 0; nt < 4; nt++)
                    mma_m16n8k8(c[mt][nt], af[mt], bf[nt]);
        }
        __syncthreads();
    }

    #pragma unroll
    for (int mt = 0; mt < 4; mt++) {
        int row0 = m0 + wm * 64 + mt * 16 + g;
        #pragma unroll
        for (int nt = 0; nt < 4; nt++) {
            int col = n0 + wn * 32 + nt * 8 + 2 * tig;
            float b0 = 0.f, b1 = 0.f;
            if (BIAS) { b0 = bias[col]; b1 = bias[col + 1]; }
            if (row0 < M) {
                float2 o = make_float2(c[mt][nt][0] + b0, c[mt][nt][1] + b1);
                *(float2*)(C + (size_t)row0 * N + col) = o;
            }
            if (row0 + 8 < M) {
                float2 o = make_float2(c[mt][nt][2] + b0, c[mt][nt][3] + b1);
                *(float2*)(C + (size_t)(row0 + 8) * N + col) = o;
            }
        }
    }
}

// ============================================================================
// K2: gating (unchanged)
// ============================================================================
__global__ __launch_bounds__(256) void gate_kernel(
    const float* __restrict__ x, const float* __restrict__ tw,
    const float* __restrict__ tb, float* __restrict__ gate)
{
    int row = blockIdx.x * 8 + (threadIdx.x >> 5);
    if (row >= MROWS) return;
    int lane = threadIdx.x & 31;
    const float* xr = x + (size_t)row * CC;
    float s0 = 0.f, s1 = 0.f, s2 = 0.f, s3 = 0.f;
    for (int c = lane; c < CC; c += 32) {
        float xv = xr[c];
        float4 w = *(const float4*)(tw + c * 4);
        s0 += xv * w.x; s1 += xv * w.y; s2 += xv * w.z; s3 += xv * w.w;
    }
    s0 = warp_sum(s0); s1 = warp_sum(s1); s2 = warp_sum(s2); s3 = warp_sum(s3);
    float l0 = s0 + tb[0], l1 = s1 + tb[1], l2 = s2 + tb[2], l3 = s3 + tb[3];
    float m = fmaxf(fmaxf(l0, l1), fmaxf(l2, l3));
    float e0 = __expf(l0 - m), e1 = __expf(l1 - m);
    float e2 = __expf(l2 - m), e3 = __expf(l3 - m);
    float inv = 1.f / (e0 + e1 + e2 + e3);
    if (lane == 0) {
        float4 o = make_float4(e0 * inv, e1 * inv, e2 * inv, e3 * inv);
        *(float4*)(gate + (size_t)row * 4) = o;
    }
}

// ============================================================================
// K3: tensor-core attention. One CTA per (b,h,n).
// S = Q K^T via split-tf32 (hi*hi + hi*lo + lo*hi => ~fp32-accurate logits).
// Nested-window softmax folded with gate coeffs (fp32), P rounded to tf32.
// O = P V via plain tf32 mma.
// Pitches: QP/KP = 68 (=4 mod 32), VP = 72 (=8 mod 32), PP = 260 (=4 mod 32)
// => all fragment loads bank-conflict-free.
// ============================================================================
#define QP 68
#define KP 68
#define VP 72
#define PP 260
#define ATTN_SMEM_FLOATS (64*QP*2 + 64*KP*2 + 248*VP + 64*PP)
#define ATTN_SMEM_BYTES  (ATTN_SMEM_FLOATS * 4)

__global__ __launch_bounds__(256) void attn_tc_kernel(
    const float* __restrict__ qkv, const float* __restrict__ gate,
    float* __restrict__ eo)
{
    extern __shared__ float sm[];
    float* sQh = sm;                    // [64][QP]
    float* sQl = sQh + 64 * QP;         // [64][QP]
    float* sKh = sQl + 64 * QP;         // [64][KP]
    float* sKl = sKh + 64 * KP;         // [64][KP]
    float* sV  = sKl + 64 * KP;         // [248][VP] (tf32 values)
    float* sP  = sV + 248 * VP;         // [64][PP]

    const int tid  = threadIdx.x;
    const int warp = tid >> 5, lane = tid & 31;
    const int g    = lane >> 2, tig = lane & 3;
    const int wm   = warp & 1,  wn  = warp >> 1;   // 2m x 4n warp grid
    const int bid  = blockIdx.x;
    const int b = bid / (HH * NJ);
    const int h = (bid / NJ) % HH;
    const int n = bid % NJ;
    const float scale = 0.125f;

    // ---- load V once (tf32), zero-pad rows [243,248) ----
    for (int i = tid; i < 248 * 16; i += 256) {
        int s = i >> 4, c4 = (i & 15) * 4;
        uint4 vt = make_uint4(0u, 0u, 0u, 0u);
        if (s < TT) {
            const float* src = qkv + ((size_t)((b * TT + s) * NJ + n)) * NQKV + h * HD + 1024;
            float4 vv = *(const float4*)(src + c4);
            vt.x = f2tf32(vv.x); vt.y = f2tf32(vv.y);
            vt.z = f2tf32(vv.z); vt.w = f2tf32(vv.w);
        }
        *(uint4*)&sV[s * VP + c4] = vt;
    }

    for (int t0 = 0; t0 < TT; t0 += 64) {
        // ---- load Q tile, split hi/lo ----
        for (int i = tid; i < 64 * 16; i += 256) {
            int r = i >> 4, c4 = (i & 15) * 4;
            int t = t0 + r;
            float4 qv = (t < TT)
                ? *(const float4*)(qkv + ((size_t)((b * TT + t) * NJ + n)) * NQKV + h * HD + c4)
                : make_float4(0.f, 0.f, 0.f, 0.f);
            uint4 hi, lo;
            hi.x = f2tf32(qv.x); lo.x = f2tf32(qv.x - __uint_as_float(hi.x));
            hi.y = f2tf32(qv.y); lo.y = f2tf32(qv.y - __uint_as_float(hi.y));
            hi.z = f2tf32(qv.z); lo.z = f2tf32(qv.z - __uint_as_float(hi.z));
            hi.w = f2tf32(qv.w); lo.w = f2tf32(qv.w - __uint_as_float(hi.w));
            *(uint4*)&sQh[r * QP + c4] = hi;
            *(uint4*)&sQl[r * QP + c4] = lo;
        }

        // ---- S = Q K^T over 4 K-chunks of 64 ----
        for (int s0 = 0; s0 < 256; s0 += 64) {
            __syncthreads();   // prior chunk's mma / prior tile's PV done
            for (int i = tid; i < 64 * 16; i += 256) {
                int sl = i >> 4, c4 = (i & 15) * 4;
                int s = s0 + sl;
                float4 kv = (s < TT)
                    ? *(const float4*)(qkv + ((size_t)((b * TT + s) * NJ + n)) * NQKV + h * HD + 512 + c4)
                    : make_float4(0.f, 0.f, 0.f, 0.f);
                uint4 hi, lo;
                hi.x = f2tf32(kv.x); lo.x = f2tf32(kv.x - __uint_as_float(hi.x));
                hi.y = f2tf32(kv.y); lo.y = f2tf32(kv.y - __uint_as_float(hi.y));
                hi.z = f2tf32(kv.z); lo.z = f2tf32(kv.z - __uint_as_float(hi.z));
                hi.w = f2tf32(kv.w); lo.w = f2tf32(kv.w - __uint_as_float(hi.w));
                *(uint4*)&sKh[sl * KP + c4] = hi;
                *(uint4*)&sKl[sl * KP + c4] = lo;
            }
            __syncthreads();

            float acc[2][2][4];
            #pragma unroll
            for (int i = 0; i < 2; i++)
                #pragma unroll
                for (int j = 0; j < 2; j++)
                    #pragma unroll
                    for (int f = 0; f < 4; f++) acc[i][j][f] = 0.f;

            #pragma unroll
            for (int kk = 0; kk < 64; kk += 8) {
                uint32_t ah[2][4], al[2][4];
                #pragma unroll
                for (int mt = 0; mt < 2; mt++) {
                    int base = wm * 32 + mt * 16;
                    ah[mt][0] = __float_as_uint(sQh[(base + g)     * QP + kk + tig]);
                    ah[mt][1] = __float_as_uint(sQh[(base + g + 8) * QP + kk + tig]);
                    ah[mt][2] = __float_as_uint(sQh[(base + g)     * QP + kk + tig + 4]);
                    ah[mt][3] = __float_as_uint(sQh[(base + g + 8) * QP + kk + tig + 4]);
                    al[mt][0] = __float_as_uint(sQl[(base + g)     * QP + kk + tig]);
                    al[mt][1] = __float_as_uint(sQl[(base + g + 8) * QP + kk + tig]);
                    al[mt][2] = __float_as_uint(sQl[(base + g)     * QP + kk + tig + 4]);
                    al[mt][3] = __float_as_uint(sQl[(base + g + 8) * QP + kk + tig + 4]);
                }
                uint32_t bh[2][2], bl[2][2];
                #pragma unroll
                for (int nt = 0; nt < 2; nt++) {
                    int nl = wn * 16 + nt * 8 + g;
                    bh[nt][0] = __float_as_uint(sKh[nl * KP + kk + tig]);
                    bh[nt][1] = __float_as_uint(sKh[nl * KP + kk + tig + 4]);
                    bl[nt][0] = __float_as_uint(sKl[nl * KP + kk + tig]);
                    bl[nt][1] = __float_as_uint(sKl[nl * KP + kk + tig + 4]);
                }
                #pragma unroll
                for (int mt = 0; mt < 2; mt++)
                    #pragma unroll
                    for (int nt = 0; nt < 2; nt++) {
                        mma_m16n8k8(acc[mt][nt], ah[mt], bh[nt]);
                        mma_m16n8k8(acc[mt][nt], ah[mt], bl[nt]);
                        mma_m16n8k8(acc[mt][nt], al[mt], bh[nt]);
                    }
            }

            // write S chunk (fp32) into sP
            #pragma unroll
            for (int mt = 0; mt < 2; mt++) {
                int row = wm * 32 + mt * 16 + g;
                #pragma unroll
                for (int nt = 0; nt < 2; nt++) {
                    int col = s0 + wn * 16 + nt * 8 + 2 * tig;
                    *(float2*)&sP[row * PP + col] =
                        make_float2(acc[mt][nt][0] * scale, acc[mt][nt][1] * scale);
                    *(float2*)&sP[(row + 8) * PP + col] =
                        make_float2(acc[mt][nt][2] * scale, acc[mt][nt][3] * scale);
                }
            }
        }
        __syncthreads();

        // ---- nested-window softmax + gate folding; write back tf32 ----
        for (int rr = 0; rr < 8; rr++) {
            int r = warp * 8 + rr;
            int t = t0 + r;
            if (t >= TT) break;
            float p[8];
            float m = -1e30f;
            #pragma unroll
            for (int i2 = 0; i2 < 8; i2++) {
                int s = lane + 32 * i2;
                float v = (s < TT) ? sP[r * PP + s] : -1e30f;
                p[i2] = v;
                m = fmaxf(m, v);
            }
            m = warp_max(m);
            int a9 = (t / 9) * 9, a27 = (t / 27) * 27, a81 = (t / 81) * 81;
            float z9 = 0.f, z27 = 0.f, z81 = 0.f, z243 = 0.f;
            #pragma unroll
            for (int i2 = 0; i2 < 8; i2++) {
                int s = lane + 32 * i2;
                float e = (s < TT) ? __expf(p[i2] - m) : 0.f;
                p[i2] = e;
                z243 += e;
                if (s >= a81 && s < a81 + 81) z81 += e;
                if (s >= a27 && s < a27 + 27) z27 += e;
                if (s >= a9  && s < a9  + 9)  z9  += e;
            }
            z9 = warp_sum(z9); z27 = warp_sum(z27);
            z81 = warp_sum(z81); z243 = warp_sum(z243);
            const float* gr = gate + ((size_t)((b * TT + t) * NJ + n)) * 4;
            float w9 = gr[0] / z9, w27 = gr[1] / z27;
            float w81 = gr[2] / z81, w243 = gr[3] / z243;
            #pragma unroll
            for (int i2 = 0; i2 < 8; i2++) {
                int s = lane + 32 * i2;
                if (s < 248) {
                    float val = 0.f;
                    if (s < TT) {
                        float cf = w243;
                        if (s >= a81 && s < a81 + 81) cf += w81;
                        if (s >= a27 && s < a27 + 27) cf += w27;
                        if (s >= a9  && s < a9  + 9)  cf += w9;
                        val = __uint_as_float(f2tf32(p[i2] * cf));
                    }
                    sP[r * PP + s] = val;
                }
            }
        }
        // rows with t >= TT: S chunks wrote zeros there (Q padded 0); values are
        // finite, and their O rows are never stored — but we still must round
        // them for the mma A path; zeros are already valid tf32.
        __syncthreads();

        // ---- O = P V  (plain tf32 mma), k over 248 ----
        {
            float acc2[2][2][4];
            #pragma unroll
            for (int i = 0; i < 2; i++)
                #pragma unroll
                for (int j = 0; j < 2; j++)
                    #pragma unroll
                    for (int f = 0; f < 4; f++) acc2[i][j][f] = 0.f;

            for (int kk = 0; kk < 248; kk += 8) {
                uint32_t af[2][4];
                #pragma unroll
                for (int mt = 0; mt < 2; mt++) {
                    int base = wm * 32 + mt * 16;
                    af[mt][0] = __float_as_uint(sP[(base + g)     * PP + kk + tig]);
                    af[mt][1] = __float_as_uint(sP[(base + g + 8) * PP + kk + tig]);
                    af[mt][2] = __float_as_uint(sP[(base + g)     * PP + kk + tig + 4]);
                    af[mt][3] = __float_as_uint(sP[(base + g + 8) * PP + kk + tig + 4]);
                }
                uint32_t bf[2][2];
                #pragma unroll
                for (int nt = 0; nt < 2; nt++) {
                    int nc = wn * 16 + nt * 8 + g;
                    bf[nt][0] = __float_as_uint(sV[(kk + tig)     * VP + nc]);
                    bf[nt][1] = __float_as_uint(sV[(kk + tig + 4) * VP + nc]);
                }
                #pragma unroll
                for (int mt = 0; mt < 2; mt++)
                    #pragma unroll
                    for (int nt = 0; nt < 2; nt++)
                        mma_m16n8k8(acc2[mt][nt], af[mt], bf[nt]);
            }

            #pragma unroll
            for (int mt = 0; mt < 2; mt++) {
                int row = wm * 32 + mt * 16 + g;
                #pragma unroll
                for (int nt = 0; nt < 2; nt++) {
                    int col = wn * 16 + nt * 8 + 2 * tig;
                    int t = t0 + row;
                    if (t < TT) {
                        *(float2*)(eo + ((size_t)((b * TT + t) * NJ + n)) * CC + h * HD + col) =
                            make_float2(acc2[mt][nt][0], acc2[mt][nt][1]);
                    }
                    if (t + 8 < TT) {
                        *(float2*)(eo + ((size_t)((b * TT + t + 8) * NJ + n)) * CC + h * HD + col) =
                            make_float2(acc2[mt][nt][2], acc2[mt][nt][3]);
                    }
                }
            }
        }
        __syncthreads();
    }
}

// ============================================================================
extern "C" void kernel_launch(void* const* d_in, const int* in_sizes, int n_in,
                              void* d_out, int out_size)
{
    const float* x      = (const float*)d_in[0];
    const float* qkv_w  = (const float*)d_in[1];
    const float* proj_w = (const float*)d_in[2];
    const float* proj_b = (const float*)d_in[3];
    const float* te_w   = (const float*)d_in[4];
    const float* te_b   = (const float*)d_in[5];
    float* out = (float*)d_out;

    float *qkv_p, *gate_p, *eo_p;
    cudaGetSymbolAddress((void**)&qkv_p,  g_qkv);
    cudaGetSymbolAddress((void**)&gate_p, g_gate);
    cudaGetSymbolAddress((void**)&eo_p,   g_eo);

    cudaFuncSetAttribute(attn_tc_kernel, cudaFuncAttributeMaxDynamicSharedMemorySize,
                         ATTN_SMEM_BYTES);

    // K1: qkv = x @ qkv_w   (16524 x 1536 x 512)  — tf32 tensor cores
    gemm_tf32<false><<<dim3(NQKV / 128, (MROWS + 127) / 128), 256>>>(
        x, qkv_w, nullptr, qkv_p, MROWS, NQKV, CC);

    // K2: gate = softmax(x @ te_w + te_b)
    gate_kernel<<<(MROWS + 7) / 8, 256>>>(x, te_w, te_b, gate_p);

    // K3: tensor-core multi-window attention + expert recombination
    attn_tc_kernel<<<BB * HH * NJ, 256, ATTN_SMEM_BYTES>>>(qkv_p, gate_p, eo_p);

    // K4: out = eo @ proj_w + proj_b   (16524 x 512 x 512) — tf32 tensor cores
    gemm_tf32<true><<<dim3(CC / 128, (MROWS + 127) / 128), 256>>>(
        eo_p, proj_w, proj_b, out, MROWS, CC, CC);
}